// round 15
// baseline (speedup 1.0000x reference)
#include <cuda_runtime.h>
#include <math.h>

// ---------------- problem constants ----------------
#define BATCH 4
#define C1    64
#define H1    224
#define W1    224
#define C2    128
#define H2    112
#define W2    112
#define HP    114
#define WP    114
#define HW2   (H2*W2)      // 12544
#define HWP   (HP*WP)      // 12996
#define COFF  18
#define K2    (C1*9)       // 576
#define K4    (C2*9)       // 1152
#define NT128 98           // 128-px tiles per image
#define GB2   (BATCH*NT128) // 392 GEMM blocks
#define NOFF  98

// GEMM smem strides (words)
#define XST 136   // X rows: conflict-free for scalar a-loads
#define WST 132   // W rows: conflict-free for uint4 b-loads

// offsets-kernel smem strides
#define XSO 136
#define WSO 40

// ---------------- scratch (__device__ globals; zero-init, no allocation) ----------------
__device__ float    g_poolpad[BATCH*C1*HWP];        // raw pooled conv1+relu, zero border
__device__ float    g_h2pad[BATCH*C2*HWP];          // raw relu(conv2+bias), zero border
__device__ float    g_xoff[(size_t)BATCH*K4*HW2];   // deform X (tf32, BN2 folded), rows ic*9+n
__device__ unsigned g_w2h[K2*C2];                   // conv2 W^T tf32, frag-permuted [k][g*16+nt]
__device__ unsigned g_w4h[K4*C2];                   // conv4 W^T tf32, frag-permuted
__device__ unsigned g_wOh[K4*32];                   // offsets W^T padded to 32 oc
__device__ float    g_p1s[C1*784], g_p1q[C1*784];   // BN1 per-block partials
__device__ float    g_p2s[C2*GB2], g_p2q[C2*GB2];   // BN2 per-block partials
__device__ float    g_scale1[C1], g_shift1[C1];
__device__ float    g_scale2[C2], g_shift2[C2];

// ---------------- helpers ----------------
__device__ __forceinline__ unsigned f2tf32(float f) {
    unsigned r; asm("cvt.rna.tf32.f32 %0, %1;" : "=r"(r) : "f"(f)); return r;
}
__device__ __forceinline__ void mma_tf32(float& d0, float& d1, float& d2, float& d3,
                                         unsigned a0, unsigned a1, unsigned a2, unsigned a3,
                                         unsigned b0, unsigned b1) {
    asm volatile("mma.sync.aligned.m16n8k8.row.col.f32.tf32.tf32.f32 "
                 "{%0,%1,%2,%3},{%4,%5,%6,%7},{%8,%9},{%0,%1,%2,%3};"
                 : "+f"(d0), "+f"(d1), "+f"(d2), "+f"(d3)
                 : "r"(a0), "r"(a1), "r"(a2), "r"(a3), "r"(b0), "r"(b1));
}
__device__ __forceinline__ void cp16(void* dst, const void* src) {
    unsigned d = (unsigned)__cvta_generic_to_shared(dst);
    asm volatile("cp.async.cg.shared.global [%0], [%1], 16;" :: "r"(d), "l"(src));
}
__device__ __forceinline__ void cp_commit() { asm volatile("cp.async.commit_group;"); }
__device__ __forceinline__ void cp_wait1()  { asm volatile("cp.async.wait_group 1;" ::: "memory"); }
__device__ __forceinline__ void cp_wait0()  { asm volatile("cp.async.wait_group 0;" ::: "memory"); }

// ---------------- weight prep: tf32 round + permute (ic-major K: k = ic*9+n) ----------------
__global__ void __launch_bounds__(256)
split_w_kernel(const float* __restrict__ w, unsigned* __restrict__ wh,
               int C_in)
{
    int idx = blockIdx.x * 256 + threadIdx.x;
    int total = C_in * 9 * 128;
    if (idx >= total) return;
    int rem = idx & 127;
    int k   = idx >> 7;
    int g   = rem >> 4, nt = rem & 15;
    int oc  = nt*8 + g;
    int ic = k / 9, n = k % 9;
    wh[idx] = f2tf32(w[((size_t)oc*C_in + ic)*9 + n]);
}

__global__ void __launch_bounds__(256)
split_w_pad_kernel(const float* __restrict__ w, unsigned* __restrict__ wh)
{
    int idx = blockIdx.x * 256 + threadIdx.x;
    int total = K4 * 32;
    if (idx >= total) return;
    int oc = idx % 32;
    int r  = idx / 32;
    int ic = r / 9, n = r % 9;
    float v = (oc < COFF) ? w[((size_t)oc*C2 + ic)*9 + n] : 0.f;
    wh[idx] = f2tf32(v);
}

// ---------------- conv1 fused: conv + bias + relu + BN1 partials + 2x2 pool ----------------
__global__ void __launch_bounds__(128)
conv1_fused_kernel(const float* __restrict__ x, const float* __restrict__ wgt,
                   const float* __restrict__ bias)
{
    __shared__ float s_in[3][18][18];
    __shared__ float s_w[8][3][9];
    __shared__ float s_red[2][8][4];

    const int tileX  = (blockIdx.x % 14) * 16;
    const int tileY  = (blockIdx.x / 14) * 16;
    const int ocBase = blockIdx.y * 8;
    const int b      = blockIdx.z;
    const int tid    = threadIdx.x;
    const int tx     = tid & 15;
    const int ty     = tid >> 4;

    for (int e = tid; e < 3*18*18; e += 128) {
        int ic = e / 324;
        int r  = (e / 18) % 18;
        int c  = e % 18;
        int gy = tileY + r - 1, gx = tileX + c - 1;
        float v = 0.f;
        if (gy >= 0 && gy < H1 && gx >= 0 && gx < W1)
            v = x[(((size_t)b*3 + ic)*H1 + gy)*W1 + gx];
        s_in[ic][r][c] = v;
    }
    for (int e = tid; e < 8*27; e += 128) {
        int oc = e / 27, r = e % 27;
        int ic = r / 9, k = r % 9;
        s_w[oc][ic][k] = wgt[((size_t)(ocBase+oc)*3 + ic)*9 + k];
    }
    __syncthreads();

    float acc0[8], acc1[8];
#pragma unroll
    for (int i = 0; i < 8; i++) { acc0[i] = 0.f; acc1[i] = 0.f; }
    const int y0 = ty * 2;
#pragma unroll
    for (int ic = 0; ic < 3; ic++) {
        float r[4][3];
#pragma unroll
        for (int rr = 0; rr < 4; rr++)
#pragma unroll
            for (int cc = 0; cc < 3; cc++)
                r[rr][cc] = s_in[ic][y0+rr][tx+cc];
#pragma unroll
        for (int oc = 0; oc < 8; oc++) {
            float a0 = acc0[oc], a1 = acc1[oc];
#pragma unroll
            for (int k = 0; k < 9; k++) {
                float wv = s_w[oc][ic][k];
                a0 = fmaf(r[k/3  ][k%3], wv, a0);
                a1 = fmaf(r[k/3+1][k%3], wv, a1);
            }
            acc0[oc] = a0; acc1[oc] = a1;
        }
    }

    const int warp = tid >> 5, lane = tid & 31;
    const int prow = (tileY >> 1) + ty + 1;
    const int pcol = (tileX >> 1) + (tx >> 1) + 1;
    const int blkId = blockIdx.x + 196 * blockIdx.z;

#pragma unroll
    for (int oc = 0; oc < 8; oc++) {
        float bv = bias[ocBase + oc];
        float v0 = fmaxf(acc0[oc] + bv, 0.f);
        float v1 = fmaxf(acc1[oc] + bv, 0.f);
        float pv = v0 + v1;
        float po = pv + __shfl_xor_sync(0xffffffffu, pv, 1);
        if ((tx & 1) == 0)
            g_poolpad[(((size_t)b*C1 + ocBase + oc)*HP + prow)*WP + pcol] = 0.25f * po;
        float s = pv, q = v0*v0 + v1*v1;
#pragma unroll
        for (int o = 16; o; o >>= 1) {
            s += __shfl_down_sync(0xffffffffu, s, o);
            q += __shfl_down_sync(0xffffffffu, q, o);
        }
        if (lane == 0) { s_red[0][oc][warp] = s; s_red[1][oc][warp] = q; }
    }
    __syncthreads();
    if (tid < 8) {
        float S = s_red[0][tid][0] + s_red[0][tid][1] + s_red[0][tid][2] + s_red[0][tid][3];
        float Q = s_red[1][tid][0] + s_red[1][tid][1] + s_red[1][tid][2] + s_red[1][tid][3];
        g_p1s[(size_t)(ocBase + tid)*784 + blkId] = S;
        g_p1q[(size_t)(ocBase + tid)*784 + blkId] = Q;
    }
}

// ---------------- BN finalize ----------------
__global__ void __launch_bounds__(256)
bn_finalize_kernel(const float* __restrict__ ps, const float* __restrict__ pq,
                   const float* __restrict__ gamma, const float* __restrict__ beta,
                   float* __restrict__ scale, float* __restrict__ shift,
                   int nblk, float inv_count)
{
    const int c = blockIdx.x;
    const int tid = threadIdx.x;
    float s = 0.f, q = 0.f;
    for (int i = tid; i < nblk; i += 256) {
        s += ps[(size_t)c*nblk + i];
        q += pq[(size_t)c*nblk + i];
    }
    __shared__ float sh[64];
#pragma unroll
    for (int o = 16; o; o >>= 1) {
        s += __shfl_down_sync(0xffffffffu, s, o);
        q += __shfl_down_sync(0xffffffffu, q, o);
    }
    int warp = tid >> 5, lane = tid & 31;
    if (lane == 0) { sh[warp] = s; sh[32+warp] = q; }
    __syncthreads();
    if (warp == 0) {
        s = (lane < 8) ? sh[lane]    : 0.f;
        q = (lane < 8) ? sh[32+lane] : 0.f;
#pragma unroll
        for (int o = 4; o; o >>= 1) {
            s += __shfl_down_sync(0xffffffffu, s, o);
            q += __shfl_down_sync(0xffffffffu, q, o);
        }
        if (lane == 0) {
            float mean = s * inv_count;
            float var  = q * inv_count - mean*mean;
            float inv  = rsqrtf(var + 1e-5f);
            float sc   = gamma[c] * inv;
            scale[c] = sc;
            shift[c] = beta[c] - mean * sc;
        }
    }
}

// ---------------- conv2 fused implicit GEMM: table-driven im2col (BN1 fold) + 1x-tf32 MMA ----------------
__global__ void __launch_bounds__(256, 2)
conv2_fused_kernel(const float* __restrict__ bias, float* __restrict__ outpad)
{
    extern __shared__ unsigned smem_u[];
    const int XB = 32*XST;
    const int WB = 32*WST;
    unsigned* sx_base = smem_u;
    unsigned* sw_base = smem_u + 2*XB;
    int*   s_poff = (int*)(sw_base + 2*WB);   // 128
    int*   s_koff = s_poff + 128;             // 576
    int*   s_kn   = s_koff + 576;             // 576
    float* s_ks   = (float*)(s_kn + 576);     // 576
    float* s_kt   = s_ks + 576;               // 576
    float* s_m    = s_kt + 576;               // 1152

    const int tid = threadIdx.x;
    const int blk = blockIdx.x;
    const int b   = blk / NT128;
    const int hw0 = (blk % NT128) * 128;
    const int lane = tid & 31, wid = tid >> 5;
    const int g = lane >> 2, t4 = lane & 3;

    // table setup
    if (tid < 128) {
        int hw = hw0 + tid;
        int h = hw / W2;
        s_poff[tid] = h*WP + (hw - h*W2);
    }
    for (int e = tid; e < 576; e += 256) {
        int ic = e / 9, n = e - ic*9;
        s_koff[e] = ic*HWP + (n/3)*WP + (n - (n/3)*3);
        s_kn[e]   = n << 7;
        s_ks[e]   = g_scale1[ic];
        s_kt[e]   = g_shift1[ic];
    }
    for (int e = tid; e < 1152; e += 256) {
        int n = e >> 7, px = e & 127;
        int hw = hw0 + px;
        int h = hw / W2, w = hw - h*W2;
        s_m[e] = ((unsigned)(h + n/3 - 1) < 112u &&
                  (unsigned)(w + n%3 - 1) < 112u) ? 1.f : 0.f;
    }

    const float* inb = g_poolpad + (size_t)b*C1*HWP;

    auto loadW = [&](int c, int buf) {
        unsigned* sw = sw_base + buf*WB;
        const uint4* h4 = (const uint4*)(g_w2h + (size_t)(c*32)*C2);
        for (int e = tid; e < 1024; e += 256) {
            int row = e >> 5, cc = e & 31;
            cp16(sw + row*WST + cc*4, h4 + e);
        }
        cp_commit();
    };
    auto gatherX = [&](int c, int buf) {
        unsigned* sx = sx_base + buf*XB;
        const int k0 = c * 32;
        const int px = tid & 127, r0 = tid >> 7;
        const int poff = s_poff[px];
#pragma unroll 4
        for (int i = 0; i < 16; i++) {
            int row = r0 + 2*i;
            int kr = k0 + row;
            float raw = inb[s_koff[kr] + poff];
            float v = raw * s_ks[kr] + s_m[s_kn[kr] + px] * s_kt[kr];
            sx[row*XST + px] = f2tf32(v);
        }
    };

    loadW(0, 0);
    __syncthreads();   // tables visible
    float acc[16][4] = {};

    const int NCHUNK = 18;
    for (int c = 0; c < NCHUNK; c++) {
        const int buf = c & 1;
        if (c + 1 < NCHUNK) loadW(c + 1, buf ^ 1);
        gatherX(c, buf);
        if (c + 1 < NCHUNK) cp_wait1(); else cp_wait0();
        __syncthreads();

        const unsigned* sx = sx_base + buf*XB;
        const unsigned* sw = sw_base + buf*WB;
#pragma unroll
        for (int ks = 0; ks < 4; ks++) {
            const unsigned* xp = sx + (ks*8 + t4)*XST + wid*16 + g;
            unsigned a0 = xp[0], a1 = xp[8], a2 = xp[4*XST], a3 = xp[4*XST+8];
            const unsigned* wp = sw + (ks*8 + t4)*WST + g*16;
#pragma unroll
            for (int j = 0; j < 4; j++) {
                uint4 br0 = *(const uint4*)(wp + j*4);
                uint4 br1 = *(const uint4*)(wp + 4*WST + j*4);
                mma_tf32(acc[4*j+0][0],acc[4*j+0][1],acc[4*j+0][2],acc[4*j+0][3],
                         a0,a1,a2,a3, br0.x, br1.x);
                mma_tf32(acc[4*j+1][0],acc[4*j+1][1],acc[4*j+1][2],acc[4*j+1][3],
                         a0,a1,a2,a3, br0.y, br1.y);
                mma_tf32(acc[4*j+2][0],acc[4*j+2][1],acc[4*j+2][2],acc[4*j+2][3],
                         a0,a1,a2,a3, br0.z, br1.z);
                mma_tf32(acc[4*j+3][0],acc[4*j+3][1],acc[4*j+3][2],acc[4*j+3][3],
                         a0,a1,a2,a3, br0.w, br1.w);
            }
        }
        __syncthreads();
    }

    const int p0 = hw0 + wid*16 + g;
    const int p1 = p0 + 8;
    float* s_red = (float*)smem_u;    // reuse X region
    const int h0 = p0 / W2, w0 = p0 - h0*W2;
    const int h1 = p1 / W2, w1 = p1 - h1*W2;
#pragma unroll
    for (int nt = 0; nt < 16; nt++) {
        int oc0 = nt*8 + 2*t4;
        int oc1 = oc0 + 1;
        float b0v = bias[oc0], b1v = bias[oc1];
        float v00 = fmaxf(acc[nt][0] + b0v, 0.f);
        float v01 = fmaxf(acc[nt][1] + b1v, 0.f);
        float v10 = fmaxf(acc[nt][2] + b0v, 0.f);
        float v11 = fmaxf(acc[nt][3] + b1v, 0.f);
        outpad[(((size_t)b*C2 + oc0)*HP + h0+1)*WP + w0+1] = v00;
        outpad[(((size_t)b*C2 + oc1)*HP + h0+1)*WP + w0+1] = v01;
        outpad[(((size_t)b*C2 + oc0)*HP + h1+1)*WP + w1+1] = v10;
        outpad[(((size_t)b*C2 + oc1)*HP + h1+1)*WP + w1+1] = v11;
        float s0 = v00 + v10, q0 = v00*v00 + v10*v10;
        float s1 = v01 + v11, q1 = v01*v01 + v11*v11;
#pragma unroll
        for (int o = 4; o <= 16; o <<= 1) {
            s0 += __shfl_xor_sync(0xffffffffu, s0, o);
            q0 += __shfl_xor_sync(0xffffffffu, q0, o);
            s1 += __shfl_xor_sync(0xffffffffu, s1, o);
            q1 += __shfl_xor_sync(0xffffffffu, q1, o);
        }
        if (g == 0) {
            s_red[(wid*128 + oc0)*2 + 0] = s0;
            s_red[(wid*128 + oc0)*2 + 1] = q0;
            s_red[(wid*128 + oc1)*2 + 0] = s1;
            s_red[(wid*128 + oc1)*2 + 1] = q1;
        }
    }
    __syncthreads();
    if (tid < 128) {
        float S = 0.f, Q = 0.f;
#pragma unroll
        for (int w = 0; w < 8; w++) {
            S += s_red[(w*128 + tid)*2 + 0];
            Q += s_red[(w*128 + tid)*2 + 1];
        }
        g_p2s[(size_t)tid*GB2 + blk] = S;
        g_p2q[(size_t)tid*GB2 + blk] = Q;
    }
}

// ---------------- offsets conv (table-driven gather) + fused bilinear params + deform gather ----------------
__global__ void __launch_bounds__(256)
offs_mma_kernel(const float* __restrict__ bias)
{
    extern __shared__ unsigned smem_u[];
    unsigned* s_x  = smem_u;                  // 72*XSO
    unsigned* s_w  = s_x + 72*XSO;            // 72*WSO
    float*    s_s  = (float*)(s_w + 72*WSO);  // 128
    float*    s_t  = s_s + C2;                // 128
    int*   s_poff = (int*)(s_t + C2);         // 128
    int*   s_koff = s_poff + 128;             // 1152
    int*   s_kn   = s_koff + 1152;            // 1152
    float* s_ks   = (float*)(s_kn + 1152);    // 1152
    float* s_kt   = s_ks + 1152;              // 1152
    float* s_m    = s_kt + 1152;              // 1152

    const int tid  = threadIdx.x;
    const int blk  = blockIdx.x;
    const int b    = blk / NOFF;
    const int hw0  = (blk % NOFF) * 128;
    const int lane = tid & 31, wid = tid >> 5;
    const int g    = lane >> 2, t4 = lane & 3;
    const int px0  = wid * 16;

    if (tid < C2) { s_s[tid] = g_scale2[tid]; s_t[tid] = g_shift2[tid]; }
    if (tid < 128) {
        int hw = hw0 + tid;
        int h = hw / W2;
        s_poff[tid] = h*WP + (hw - h*W2);
    }
    for (int e = tid; e < 1152; e += 256) {
        int ic = e / 9, n = e - ic*9;
        s_koff[e] = ic*HWP + (n/3)*WP + (n - (n/3)*3);
        s_kn[e]   = n << 7;
        s_ks[e]   = g_scale2[ic];
        s_kt[e]   = g_shift2[ic];
    }
    for (int e = tid; e < 1152; e += 256) {
        int n = e >> 7, px = e & 127;
        int hw = hw0 + px;
        int h = hw / W2, w = hw - h*W2;
        s_m[e] = ((unsigned)(h + n/3 - 1) < 112u &&
                  (unsigned)(w + n%3 - 1) < 112u) ? 1.f : 0.f;
    }

    const float* inb = g_h2pad + (size_t)b*C2*HWP;
    float acc[4][4] = {};

    for (int ic0 = 0; ic0 < C2; ic0 += 8) {
        __syncthreads();   // first iteration also covers table setup
        {
            const uint4* sh4 = (const uint4*)(g_wOh + (size_t)ic0*9*32);
            for (int e = tid; e < 576; e += 256) {
                int kr = e >> 3, c4 = e & 7;
                cp16(s_w + kr*WSO + c4*4, sh4 + e);
            }
        }
        {
            const int kbase = ic0 * 9;
            const int px = tid & 127, r0 = tid >> 7;
            const int poff = s_poff[px];
#pragma unroll 4
            for (int i = 0; i < 36; i++) {
                int row = r0 + 2*i;
                int kr = kbase + row;
                float raw = inb[s_koff[kr] + poff];
                float v = raw * s_ks[kr] + s_m[s_kn[kr] + px] * s_kt[kr];
                s_x[row*XSO + px] = f2tf32(v);
            }
        }
        cp_commit(); cp_wait0();
        __syncthreads();

#pragma unroll
        for (int ks = 0; ks < 9; ks++) {
            const unsigned* xp = s_x + (ks*8 + t4)*XSO + px0 + g;
            unsigned a0 = xp[0], a1 = xp[8], a2 = xp[4*XSO], a3 = xp[4*XSO+8];
            const unsigned* wp = s_w + (ks*8 + t4)*WSO + g;
#pragma unroll
            for (int nt = 0; nt < 4; nt++) {
                unsigned b0 = wp[nt*8], b1 = wp[4*WSO + nt*8];
                mma_tf32(acc[nt][0],acc[nt][1],acc[nt][2],acc[nt][3], a0,a1,a2,a3, b0,b1);
            }
        }
    }

    // ---- epilogue A: stage 18x128 offsets in smem ----
    __syncthreads();
    float* s_off = (float*)smem_u;   // [18][128] in s_x region
    const int p0 = px0 + g, p1 = p0 + 8;
#pragma unroll
    for (int nt = 0; nt < 4; nt++) {
        int oc0 = nt*8 + 2*t4;
        int oc1 = oc0 + 1;
        if (oc0 < COFF) {
            float bv = bias[oc0];
            s_off[oc0*128 + p0] = acc[nt][0] + bv;
            s_off[oc0*128 + p1] = acc[nt][2] + bv;
        }
        if (oc1 < COFF) {
            float bv = bias[oc1];
            s_off[oc1*128 + p0] = acc[nt][1] + bv;
            s_off[oc1*128 + p1] = acc[nt][3] + bv;
        }
    }
    __syncthreads();

    // ---- epilogue B: per (tap,px) bilinear params in regs + 128-channel gather ----
    const float* base = g_h2pad + (size_t)b*C2*HWP;
    for (int e = tid; e < 1152; e += 256) {
        int n  = e >> 7, px = e & 127;
        int hw = hw0 + px;
        int h = hw / W2, w = hw - h*W2;
        float ox = s_off[n*128 + px];
        float oy = s_off[(9+n)*128 + px];
        float pX = (float)(h + 1) + (float)(n/3 - 1) + ox;
        float pY = (float)(w + 1) + (float)(n%3 - 1) + oy;
        float fx = floorf(pX), fy = floorf(pY);
        float qltx = fminf(fmaxf(fx,     0.f), (float)(HP-1));
        float qlty = fminf(fmaxf(fy,     0.f), (float)(WP-1));
        float qrbx = fminf(fmaxf(fx+1.f, 0.f), (float)(HP-1));
        float qrby = fminf(fmaxf(fy+1.f, 0.f), (float)(WP-1));
        bool mx = (pX < 1.f) || (pX > (float)(HP-2));
        bool my = (pY < 1.f) || (pY > (float)(WP-2));
        float pxc = fminf(fmaxf(mx ? fx : pX, 0.f), (float)(HP-1));
        float pyc = fminf(fmaxf(my ? fy : pY, 0.f), (float)(WP-1));
        float glt = (1.f + (qltx - pxc)) * (1.f + (qlty - pyc));
        float grb = (1.f - (qrbx - pxc)) * (1.f - (qrby - pyc));
        float glb = (1.f + (qltx - pxc)) * (1.f - (qrby - pyc));
        float grt = (1.f - (qrbx - pxc)) * (1.f + (qlty - pyc));
        int ix0 = (int)qltx, iy0 = (int)qlty;
        int ix1 = (int)qrbx, iy1 = (int)qrby;
        float m0 = ((unsigned)(ix0-1) < 112u && (unsigned)(iy0-1) < 112u) ? 1.f : 0.f;
        float m1 = ((unsigned)(ix1-1) < 112u && (unsigned)(iy1-1) < 112u) ? 1.f : 0.f;
        float m2 = ((unsigned)(ix0-1) < 112u && (unsigned)(iy1-1) < 112u) ? 1.f : 0.f;
        float m3 = ((unsigned)(ix1-1) < 112u && (unsigned)(iy0-1) < 112u) ? 1.f : 0.f;
        float ts = glt*m0 + grb*m1 + glb*m2 + grt*m3;
        int i00 = ix0*WP + iy0;
        int i11 = ix1*WP + iy1;
        int i01 = ix0*WP + iy1;
        int i10 = ix1*WP + iy0;

        const float* plane = base;
        float* outp = g_xoff + ((size_t)b*K4 + n)*HW2 + hw;
#pragma unroll 4
        for (int ic = 0; ic < C2; ic++) {
            float raw = glt * __ldg(plane + i00)
                      + grb * __ldg(plane + i11)
                      + glb * __ldg(plane + i01)
                      + grt * __ldg(plane + i10);
            float v = raw * s_s[ic] + ts * s_t[ic];
            *outp = __uint_as_float(f2tf32(v));
            plane += HWP;
            outp  += (size_t)9*HW2;
        }
    }
}

// ---------------- deform GEMM: double-buffered 1x-tf32 MMA, 128px x 128oc, kchunk=32 ----------------
__global__ void __launch_bounds__(256, 2)
gemm1x_kernel(const float* __restrict__ X, const unsigned* __restrict__ Wh,
              float* __restrict__ out)
{
    extern __shared__ unsigned smem_u[];
    const int XB = 32*XST;
    const int WB = 32*WST;
    unsigned* sx_base = smem_u;
    unsigned* sw_base = smem_u + 2*XB;

    const int tid = threadIdx.x;
    const int blk = blockIdx.x;
    const int b   = blk / NT128;
    const int hw0 = (blk % NT128) * 128;
    const int lane = tid & 31, wid = tid >> 5;
    const int g = lane >> 2, t4 = lane & 3;

    const int NCHUNK = 36;
    const float* Xb = X + (size_t)b*K4*HW2 + hw0;

    auto load_chunk = [&](int c, int buf) {
        const int k0 = c * 32;
        unsigned* sx = sx_base + buf*XB;
        unsigned* sw = sw_base + buf*WB;
        const uint4* h4 = (const uint4*)(Wh + (size_t)k0*C2);
        for (int e = tid; e < 1024; e += 256) {
            int row = e >> 5, cc = e & 31;
            cp16(sx + row*XST + cc*4, Xb + (size_t)(k0+row)*HW2 + cc*4);
            cp16(sw + row*WST + cc*4, h4 + e);
        }
        cp_commit();
    };

    load_chunk(0, 0);
    float acc[16][4] = {};

    for (int c = 0; c < NCHUNK; c++) {
        const int buf = c & 1;
        cp_wait0();
        __syncthreads();
        if (c + 1 < NCHUNK) load_chunk(c + 1, buf ^ 1);

        const unsigned* sx = sx_base + buf*XB;
        const unsigned* sw = sw_base + buf*WB;
#pragma unroll
        for (int ks = 0; ks < 4; ks++) {
            const unsigned* xp = sx + (ks*8 + t4)*XST + wid*16 + g;
            unsigned a0 = xp[0], a1 = xp[8], a2 = xp[4*XST], a3 = xp[4*XST+8];
            const unsigned* wp = sw + (ks*8 + t4)*WST + g*16;
#pragma unroll
            for (int j = 0; j < 4; j++) {
                uint4 br0 = *(const uint4*)(wp + j*4);
                uint4 br1 = *(const uint4*)(wp + 4*WST + j*4);
                mma_tf32(acc[4*j+0][0],acc[4*j+0][1],acc[4*j+0][2],acc[4*j+0][3],
                         a0,a1,a2,a3, br0.x, br1.x);
                mma_tf32(acc[4*j+1][0],acc[4*j+1][1],acc[4*j+1][2],acc[4*j+1][3],
                         a0,a1,a2,a3, br0.y, br1.y);
                mma_tf32(acc[4*j+2][0],acc[4*j+2][1],acc[4*j+2][2],acc[4*j+2][3],
                         a0,a1,a2,a3, br0.z, br1.z);
                mma_tf32(acc[4*j+3][0],acc[4*j+3][1],acc[4*j+3][2],acc[4*j+3][3],
                         a0,a1,a2,a3, br0.w, br1.w);
            }
        }
        __syncthreads();
    }

    const int p0 = hw0 + wid*16 + g;
    const int p1 = p0 + 8;
#pragma unroll
    for (int nt = 0; nt < 16; nt++) {
        int oc0 = nt*8 + 2*t4;
        int oc1 = oc0 + 1;
        out[((size_t)b*C2 + oc0)*HW2 + p0] = acc[nt][0];
        out[((size_t)b*C2 + oc1)*HW2 + p0] = acc[nt][1];
        out[((size_t)b*C2 + oc0)*HW2 + p1] = acc[nt][2];
        out[((size_t)b*C2 + oc1)*HW2 + p1] = acc[nt][3];
    }
}

// ---------------- launch ----------------
extern "C" void kernel_launch(void* const* d_in, const int* in_sizes, int n_in,
                              void* d_out, int out_size)
{
    const float* x       = (const float*)d_in[0];
    const float* conv1_w = (const float*)d_in[1];
    const float* conv1_b = (const float*)d_in[2];
    const float* bn1_g   = (const float*)d_in[3];
    const float* bn1_b   = (const float*)d_in[4];
    const float* conv2_w = (const float*)d_in[5];
    const float* conv2_b = (const float*)d_in[6];
    const float* bn2_g   = (const float*)d_in[7];
    const float* bn2_b   = (const float*)d_in[8];
    const float* off_w   = (const float*)d_in[9];
    const float* off_b   = (const float*)d_in[10];
    const float* conv4_w = (const float*)d_in[11];
    float* out = (float*)d_out;

    float *p_s1, *p_t1, *p_s2, *p_t2, *p_h2pad, *p_xoff;
    float *p_p1s, *p_p1q, *p_p2s, *p_p2q;
    unsigned *p_w2h, *p_w4h, *p_wOh;
    cudaGetSymbolAddress((void**)&p_s1,    g_scale1);
    cudaGetSymbolAddress((void**)&p_t1,    g_shift1);
    cudaGetSymbolAddress((void**)&p_s2,    g_scale2);
    cudaGetSymbolAddress((void**)&p_t2,    g_shift2);
    cudaGetSymbolAddress((void**)&p_h2pad, g_h2pad);
    cudaGetSymbolAddress((void**)&p_xoff,  g_xoff);
    cudaGetSymbolAddress((void**)&p_p1s,   g_p1s);
    cudaGetSymbolAddress((void**)&p_p1q,   g_p1q);
    cudaGetSymbolAddress((void**)&p_p2s,   g_p2s);
    cudaGetSymbolAddress((void**)&p_p2q,   g_p2q);
    cudaGetSymbolAddress((void**)&p_w2h,   g_w2h);
    cudaGetSymbolAddress((void**)&p_w4h,   g_w4h);
    cudaGetSymbolAddress((void**)&p_wOh,   g_wOh);

    const int SMEM_GEMM = (2*32*XST + 2*32*WST) * 4;                     // 68608 B
    const int SMEM_C2F  = SMEM_GEMM + (128 + 3*576 + 2*576 + 1152) * 4;  // +14.3 KB
    const int SMEM_OFFS = (72*XSO + 72*WSO + 2*C2 + 128 + 5*1152) * 4;   // ~75.3 KB
    cudaFuncSetAttribute(conv2_fused_kernel,
                         cudaFuncAttributeMaxDynamicSharedMemorySize, SMEM_C2F);
    cudaFuncSetAttribute(gemm1x_kernel,
                         cudaFuncAttributeMaxDynamicSharedMemorySize, SMEM_GEMM);
    cudaFuncSetAttribute(offs_mma_kernel,
                         cudaFuncAttributeMaxDynamicSharedMemorySize, SMEM_OFFS);

    // 0) weight preprocessing (tf32 round + fragment-permuted transpose)
    split_w_kernel<<<(K2*C2 + 255)/256, 256>>>(conv2_w, p_w2h, C1);
    split_w_kernel<<<(K4*C2 + 255)/256, 256>>>(conv4_w, p_w4h, C2);
    split_w_pad_kernel<<<(K4*32 + 255)/256, 256>>>(off_w, p_wOh);

    // 1) conv1 + bias + relu + BN1 partials + 2x2 pool
    {
        dim3 grid(196, 8, BATCH);
        conv1_fused_kernel<<<grid, 128>>>(x, conv1_w, conv1_b);
    }
    // 2) BN1 finalize
    bn_finalize_kernel<<<C1, 256>>>(p_p1s, p_p1q, bn1_g, bn1_b, p_s1, p_t1,
                                    784, 1.0f/(float)(BATCH*H1*W1));
    // 3) conv2 fused implicit GEMM (BN1 folded) -> raw padded h2 + BN2 partials
    conv2_fused_kernel<<<GB2, 256, SMEM_C2F>>>(conv2_b, p_h2pad);
    // 4) BN2 finalize
    bn_finalize_kernel<<<C2, 256>>>(p_p2s, p_p2q, bn2_g, bn2_b, p_s2, p_t2,
                                    GB2, 1.0f/(float)(BATCH*HW2));
    // 5) offsets conv (BN2 folded) + fused bilinear params + fused deform gather
    offs_mma_kernel<<<BATCH*NOFF, 256, SMEM_OFFS>>>(off_b);
    // 6) deform GEMM -> d_out
    gemm1x_kernel<<<GB2, 256, SMEM_GEMM>>>(p_xoff, p_w4h, out);
}

// round 16
// speedup vs baseline: 1.0577x; 1.0577x over previous
#include <cuda_runtime.h>
#include <math.h>

// ---------------- problem constants ----------------
#define BATCH 4
#define C1    64
#define H1    224
#define W1    224
#define C2    128
#define H2    112
#define W2    112
#define HP    114
#define WP    114
#define HW2   (H2*W2)      // 12544
#define HWP   (HP*WP)      // 12996
#define COFF  18
#define K2    (C1*9)       // 576
#define K4    (C2*9)       // 1152
#define NT128 98           // 128-px tiles per image
#define GB2   (BATCH*NT128) // 392 GEMM blocks
#define NOFF  98
#define NB1   392          // conv1 blocks per channel (98 tiles x 4 batch)

// GEMM smem strides (words)
#define XST 136   // X rows: conflict-free for scalar a-loads
#define WST 132   // W rows: conflict-free for uint4 b-loads

// offsets-kernel smem strides
#define XSO 136
#define WSO 40

// ---------------- scratch (__device__ globals; zero-init, no allocation) ----------------
__device__ float    g_poolpad[BATCH*C1*HWP];        // raw pooled conv1+relu, zero border
__device__ float    g_h2pad[BATCH*C2*HWP];          // raw relu(conv2+bias), zero border
__device__ float    g_xoff[(size_t)BATCH*K4*HW2];   // deform X (tf32, BN2 folded), rows ic*9+n
__device__ unsigned g_w2h[K2*C2];                   // conv2 W^T tf32, frag-permuted [k][g*16+nt]
__device__ unsigned g_w4h[K4*C2];                   // conv4 W^T tf32, frag-permuted
__device__ unsigned g_wOh[K4*32];                   // offsets W^T padded to 32 oc
__device__ float    g_p1s[C1*NB1], g_p1q[C1*NB1];   // BN1 per-block partials
__device__ float    g_p2s[C2*GB2], g_p2q[C2*GB2];   // BN2 per-block partials
__device__ float    g_scale1[C1], g_shift1[C1];
__device__ float    g_scale2[C2], g_shift2[C2];

// ---------------- helpers ----------------
__device__ __forceinline__ unsigned f2tf32(float f) {
    unsigned r; asm("cvt.rna.tf32.f32 %0, %1;" : "=r"(r) : "f"(f)); return r;
}
__device__ __forceinline__ void mma_tf32(float& d0, float& d1, float& d2, float& d3,
                                         unsigned a0, unsigned a1, unsigned a2, unsigned a3,
                                         unsigned b0, unsigned b1) {
    asm volatile("mma.sync.aligned.m16n8k8.row.col.f32.tf32.tf32.f32 "
                 "{%0,%1,%2,%3},{%4,%5,%6,%7},{%8,%9},{%0,%1,%2,%3};"
                 : "+f"(d0), "+f"(d1), "+f"(d2), "+f"(d3)
                 : "r"(a0), "r"(a1), "r"(a2), "r"(a3), "r"(b0), "r"(b1));
}
__device__ __forceinline__ void cp16(void* dst, const void* src) {
    unsigned d = (unsigned)__cvta_generic_to_shared(dst);
    asm volatile("cp.async.cg.shared.global [%0], [%1], 16;" :: "r"(d), "l"(src));
}
__device__ __forceinline__ void cp_commit() { asm volatile("cp.async.commit_group;"); }
__device__ __forceinline__ void cp_wait1()  { asm volatile("cp.async.wait_group 1;" ::: "memory"); }
__device__ __forceinline__ void cp_wait0()  { asm volatile("cp.async.wait_group 0;" ::: "memory"); }

// ---------------- weight prep: tf32 round + permute (ic-major K: k = ic*9+n) ----------------
__global__ void __launch_bounds__(256)
split_w_kernel(const float* __restrict__ w, unsigned* __restrict__ wh,
               int C_in)
{
    int idx = blockIdx.x * 256 + threadIdx.x;
    int total = C_in * 9 * 128;
    if (idx >= total) return;
    int rem = idx & 127;
    int k   = idx >> 7;
    int g   = rem >> 4, nt = rem & 15;
    int oc  = nt*8 + g;
    int ic = k / 9, n = k % 9;
    wh[idx] = f2tf32(w[((size_t)oc*C_in + ic)*9 + n]);
}

__global__ void __launch_bounds__(256)
split_w_pad_kernel(const float* __restrict__ w, unsigned* __restrict__ wh)
{
    int idx = blockIdx.x * 256 + threadIdx.x;
    int total = K4 * 32;
    if (idx >= total) return;
    int oc = idx % 32;
    int r  = idx / 32;
    int ic = r / 9, n = r % 9;
    float v = (oc < COFF) ? w[((size_t)oc*C2 + ic)*9 + n] : 0.f;
    wh[idx] = f2tf32(v);
}

// ---------------- conv1 fused: 16x32 tile, 4 rows/thread; conv+bias+relu+BN1 partials+pool ----------------
__global__ void __launch_bounds__(128)
conv1_fused_kernel(const float* __restrict__ x, const float* __restrict__ wgt,
                   const float* __restrict__ bias)
{
    __shared__ float s_in[3][34][18];
    __shared__ float s_w[8][3][9];
    __shared__ float s_red[2][8][4];

    const int tileX  = (blockIdx.x % 14) * 16;
    const int tileY  = (blockIdx.x / 14) * 32;
    const int ocBase = blockIdx.y * 8;
    const int b      = blockIdx.z;
    const int tid    = threadIdx.x;
    const int tx     = tid & 15;
    const int ty     = tid >> 4;          // 0..7, 4 rows each

    for (int e = tid; e < 3*34*18; e += 128) {
        int ic = e / (34*18);
        int r  = (e / 18) % 34;
        int c  = e % 18;
        int gy = tileY + r - 1, gx = tileX + c - 1;
        float v = 0.f;
        if (gy >= 0 && gy < H1 && gx >= 0 && gx < W1)
            v = x[(((size_t)b*3 + ic)*H1 + gy)*W1 + gx];
        s_in[ic][r][c] = v;
    }
    for (int e = tid; e < 8*27; e += 128) {
        int oc = e / 27, r = e % 27;
        int ic = r / 9, k = r % 9;
        s_w[oc][ic][k] = wgt[((size_t)(ocBase+oc)*3 + ic)*9 + k];
    }
    __syncthreads();

    float acc[8][4];
#pragma unroll
    for (int i = 0; i < 8; i++)
#pragma unroll
        for (int j = 0; j < 4; j++) acc[i][j] = 0.f;

    const int y0 = ty * 4;
#pragma unroll
    for (int ic = 0; ic < 3; ic++) {
        float r[6][3];
#pragma unroll
        for (int rr = 0; rr < 6; rr++)
#pragma unroll
            for (int cc = 0; cc < 3; cc++)
                r[rr][cc] = s_in[ic][y0+rr][tx+cc];
#pragma unroll
        for (int oc = 0; oc < 8; oc++) {
#pragma unroll
            for (int k = 0; k < 9; k++) {
                float wv = s_w[oc][ic][k];
#pragma unroll
                for (int j = 0; j < 4; j++)
                    acc[oc][j] = fmaf(r[k/3 + j][k%3], wv, acc[oc][j]);
            }
        }
    }

    const int warp = tid >> 5, lane = tid & 31;
    const int prow0 = (tileY >> 1) + ty*2 + 1;    // padded pooled rows
    const int pcol  = (tileX >> 1) + (tx >> 1) + 1;
    const int blkId = blockIdx.x + 98 * blockIdx.z;   // 0..391

#pragma unroll
    for (int oc = 0; oc < 8; oc++) {
        float bv = bias[ocBase + oc];
        float v0 = fmaxf(acc[oc][0] + bv, 0.f);
        float v1 = fmaxf(acc[oc][1] + bv, 0.f);
        float v2 = fmaxf(acc[oc][2] + bv, 0.f);
        float v3 = fmaxf(acc[oc][3] + bv, 0.f);
        float pv0 = v0 + v1;
        float pv1 = v2 + v3;
        float po0 = pv0 + __shfl_xor_sync(0xffffffffu, pv0, 1);
        float po1 = pv1 + __shfl_xor_sync(0xffffffffu, pv1, 1);
        if ((tx & 1) == 0) {
            size_t base = (((size_t)b*C1 + ocBase + oc)*HP + prow0)*WP + pcol;
            g_poolpad[base]      = 0.25f * po0;
            g_poolpad[base + WP] = 0.25f * po1;
        }
        float s = pv0 + pv1;
        float q = v0*v0 + v1*v1 + v2*v2 + v3*v3;
#pragma unroll
        for (int o = 16; o; o >>= 1) {
            s += __shfl_down_sync(0xffffffffu, s, o);
            q += __shfl_down_sync(0xffffffffu, q, o);
        }
        if (lane == 0) { s_red[0][oc][warp] = s; s_red[1][oc][warp] = q; }
    }
    __syncthreads();
    if (tid < 8) {
        float S = s_red[0][tid][0] + s_red[0][tid][1] + s_red[0][tid][2] + s_red[0][tid][3];
        float Q = s_red[1][tid][0] + s_red[1][tid][1] + s_red[1][tid][2] + s_red[1][tid][3];
        g_p1s[(size_t)(ocBase + tid)*NB1 + blkId] = S;
        g_p1q[(size_t)(ocBase + tid)*NB1 + blkId] = Q;
    }
}

// ---------------- BN finalize ----------------
__global__ void __launch_bounds__(256)
bn_finalize_kernel(const float* __restrict__ ps, const float* __restrict__ pq,
                   const float* __restrict__ gamma, const float* __restrict__ beta,
                   float* __restrict__ scale, float* __restrict__ shift,
                   int nblk, float inv_count)
{
    const int c = blockIdx.x;
    const int tid = threadIdx.x;
    float s = 0.f, q = 0.f;
    for (int i = tid; i < nblk; i += 256) {
        s += ps[(size_t)c*nblk + i];
        q += pq[(size_t)c*nblk + i];
    }
    __shared__ float sh[64];
#pragma unroll
    for (int o = 16; o; o >>= 1) {
        s += __shfl_down_sync(0xffffffffu, s, o);
        q += __shfl_down_sync(0xffffffffu, q, o);
    }
    int warp = tid >> 5, lane = tid & 31;
    if (lane == 0) { sh[warp] = s; sh[32+warp] = q; }
    __syncthreads();
    if (warp == 0) {
        s = (lane < 8) ? sh[lane]    : 0.f;
        q = (lane < 8) ? sh[32+lane] : 0.f;
#pragma unroll
        for (int o = 4; o; o >>= 1) {
            s += __shfl_down_sync(0xffffffffu, s, o);
            q += __shfl_down_sync(0xffffffffu, q, o);
        }
        if (lane == 0) {
            float mean = s * inv_count;
            float var  = q * inv_count - mean*mean;
            float inv  = rsqrtf(var + 1e-5f);
            float sc   = gamma[c] * inv;
            scale[c] = sc;
            shift[c] = beta[c] - mean * sc;
        }
    }
}

// ---------------- conv2 fused implicit GEMM: in-kernel im2col (BN1 fold) + 1x-tf32 MMA ----------------
__global__ void __launch_bounds__(256, 2)
conv2_fused_kernel(const float* __restrict__ bias, float* __restrict__ outpad)
{
    extern __shared__ unsigned smem_u[];
    const int XB = 32*XST;
    const int WB = 32*WST;
    unsigned* sx_base = smem_u;
    unsigned* sw_base = smem_u + 2*XB;
    float* s_s = (float*)(sw_base + 2*WB);        // 64
    float* s_t = s_s + C1;                        // 64

    const int tid = threadIdx.x;
    const int blk = blockIdx.x;
    const int b   = blk / NT128;
    const int hw0 = (blk % NT128) * 128;
    const int lane = tid & 31, wid = tid >> 5;
    const int g = lane >> 2, t4 = lane & 3;

    if (tid < C1)        s_s[tid] = g_scale1[tid];
    else if (tid < 2*C1) s_t[tid - C1] = g_shift1[tid - C1];

    const float* inb = g_poolpad + (size_t)b*C1*HWP;

    auto loadW = [&](int c, int buf) {
        unsigned* sw = sw_base + buf*WB;
        const uint4* h4 = (const uint4*)(g_w2h + (size_t)(c*32)*C2);
        for (int e = tid; e < 1024; e += 256) {
            int row = e >> 5, cc = e & 31;
            cp16(sw + row*WST + cc*4, h4 + e);
        }
        cp_commit();
    };
    auto gatherX = [&](int c, int buf) {
        unsigned* sx = sx_base + buf*XB;
        const int k0 = c * 32;
#pragma unroll 4
        for (int e = tid; e < 4096; e += 256) {
            int row = e >> 7, px = e & 127;
            int kr = k0 + row;
            int ic = kr / 9, n = kr - ic*9;
            int hw = hw0 + px;
            int h  = hw / W2, w = hw - h*W2;
            int hh = h + n/3, ww = w + n - (n/3)*3;
            float raw = inb[(size_t)ic*HWP + hh*WP + ww];
            float m = ((unsigned)(hh-1) < 112u && (unsigned)(ww-1) < 112u) ? 1.f : 0.f;
            float v = raw * s_s[ic] + m * s_t[ic];
            sx[row*XST + px] = f2tf32(v);
        }
    };

    loadW(0, 0);
    __syncthreads();   // s_s/s_t visible
    float acc[16][4] = {};

    const int NCHUNK = 18;
    for (int c = 0; c < NCHUNK; c++) {
        const int buf = c & 1;
        if (c + 1 < NCHUNK) loadW(c + 1, buf ^ 1);
        gatherX(c, buf);
        if (c + 1 < NCHUNK) cp_wait1(); else cp_wait0();
        __syncthreads();

        const unsigned* sx = sx_base + buf*XB;
        const unsigned* sw = sw_base + buf*WB;
#pragma unroll
        for (int ks = 0; ks < 4; ks++) {
            const unsigned* xp = sx + (ks*8 + t4)*XST + wid*16 + g;
            unsigned a0 = xp[0], a1 = xp[8], a2 = xp[4*XST], a3 = xp[4*XST+8];
            const unsigned* wp = sw + (ks*8 + t4)*WST + g*16;
#pragma unroll
            for (int j = 0; j < 4; j++) {
                uint4 br0 = *(const uint4*)(wp + j*4);
                uint4 br1 = *(const uint4*)(wp + 4*WST + j*4);
                mma_tf32(acc[4*j+0][0],acc[4*j+0][1],acc[4*j+0][2],acc[4*j+0][3],
                         a0,a1,a2,a3, br0.x, br1.x);
                mma_tf32(acc[4*j+1][0],acc[4*j+1][1],acc[4*j+1][2],acc[4*j+1][3],
                         a0,a1,a2,a3, br0.y, br1.y);
                mma_tf32(acc[4*j+2][0],acc[4*j+2][1],acc[4*j+2][2],acc[4*j+2][3],
                         a0,a1,a2,a3, br0.z, br1.z);
                mma_tf32(acc[4*j+3][0],acc[4*j+3][1],acc[4*j+3][2],acc[4*j+3][3],
                         a0,a1,a2,a3, br0.w, br1.w);
            }
        }
        __syncthreads();
    }

    const int p0 = hw0 + wid*16 + g;
    const int p1 = p0 + 8;
    float* s_red = (float*)smem_u;    // [8][128][2] floats
    const int h0 = p0 / W2, w0 = p0 - h0*W2;
    const int h1 = p1 / W2, w1 = p1 - h1*W2;
#pragma unroll
    for (int nt = 0; nt < 16; nt++) {
        int oc0 = nt*8 + 2*t4;
        int oc1 = oc0 + 1;
        float b0v = bias[oc0], b1v = bias[oc1];
        float v00 = fmaxf(acc[nt][0] + b0v, 0.f);
        float v01 = fmaxf(acc[nt][1] + b1v, 0.f);
        float v10 = fmaxf(acc[nt][2] + b0v, 0.f);
        float v11 = fmaxf(acc[nt][3] + b1v, 0.f);
        outpad[(((size_t)b*C2 + oc0)*HP + h0+1)*WP + w0+1] = v00;
        outpad[(((size_t)b*C2 + oc1)*HP + h0+1)*WP + w0+1] = v01;
        outpad[(((size_t)b*C2 + oc0)*HP + h1+1)*WP + w1+1] = v10;
        outpad[(((size_t)b*C2 + oc1)*HP + h1+1)*WP + w1+1] = v11;
        float s0 = v00 + v10, q0 = v00*v00 + v10*v10;
        float s1 = v01 + v11, q1 = v01*v01 + v11*v11;
#pragma unroll
        for (int o = 4; o <= 16; o <<= 1) {
            s0 += __shfl_xor_sync(0xffffffffu, s0, o);
            q0 += __shfl_xor_sync(0xffffffffu, q0, o);
            s1 += __shfl_xor_sync(0xffffffffu, s1, o);
            q1 += __shfl_xor_sync(0xffffffffu, q1, o);
        }
        if (g == 0) {
            s_red[(wid*128 + oc0)*2 + 0] = s0;
            s_red[(wid*128 + oc0)*2 + 1] = q0;
            s_red[(wid*128 + oc1)*2 + 0] = s1;
            s_red[(wid*128 + oc1)*2 + 1] = q1;
        }
    }
    __syncthreads();
    if (tid < 128) {
        float S = 0.f, Q = 0.f;
#pragma unroll
        for (int w = 0; w < 8; w++) {
            S += s_red[(w*128 + tid)*2 + 0];
            Q += s_red[(w*128 + tid)*2 + 1];
        }
        g_p2s[(size_t)tid*GB2 + blk] = S;
        g_p2q[(size_t)tid*GB2 + blk] = Q;
    }
}

// ---------------- offsets conv + fused bilinear params + fused deform gather ----------------
__global__ void __launch_bounds__(256)
offs_mma_kernel(const float* __restrict__ bias)
{
    extern __shared__ unsigned smem_u[];
    unsigned* s_x  = smem_u;
    unsigned* s_w  = s_x + 72*XSO;
    float*    s_s  = (float*)(s_w + 72*WSO);
    float*    s_t  = s_s + C2;

    const int tid  = threadIdx.x;
    const int blk  = blockIdx.x;
    const int b    = blk / NOFF;
    const int hw0  = (blk % NOFF) * 128;
    const int lane = tid & 31, wid = tid >> 5;
    const int g    = lane >> 2, t4 = lane & 3;
    const int px0  = wid * 16;

    if (tid < C2) { s_s[tid] = g_scale2[tid]; s_t[tid] = g_shift2[tid]; }

    const float* inb = g_h2pad + (size_t)b*C2*HWP;
    float acc[4][4] = {};

    for (int ic0 = 0; ic0 < C2; ic0 += 8) {
        __syncthreads();
        {
            const uint4* sh4 = (const uint4*)(g_wOh + (size_t)ic0*9*32);
            for (int e = tid; e < 576; e += 256) {
                int kr = e >> 3, c4 = e & 7;
                cp16(s_w + kr*WSO + c4*4, sh4 + e);
            }
        }
        for (int e = tid; e < 9216; e += 256) {
            int r  = e >> 7, px = e & 127;
            int icr = r / 9, n = r - icr*9;
            int hw = hw0 + px;
            int h  = hw / W2, w = hw - h*W2;
            int hh = h + n/3, ww = w + n%3;
            float raw = inb[(size_t)(ic0+icr)*HWP + hh*WP + ww];
            float m = ((unsigned)(hh-1) < 112u && (unsigned)(ww-1) < 112u) ? 1.f : 0.f;
            float v = raw * s_s[ic0+icr] + m * s_t[ic0+icr];
            s_x[r*XSO + px] = f2tf32(v);
        }
        cp_commit(); cp_wait0();
        __syncthreads();

#pragma unroll
        for (int ks = 0; ks < 9; ks++) {
            const unsigned* xp = s_x + (ks*8 + t4)*XSO + px0 + g;
            unsigned a0 = xp[0], a1 = xp[8], a2 = xp[4*XSO], a3 = xp[4*XSO+8];
            const unsigned* wp = s_w + (ks*8 + t4)*WSO + g;
#pragma unroll
            for (int nt = 0; nt < 4; nt++) {
                unsigned b0 = wp[nt*8], b1 = wp[4*WSO + nt*8];
                mma_tf32(acc[nt][0],acc[nt][1],acc[nt][2],acc[nt][3], a0,a1,a2,a3, b0,b1);
            }
        }
    }

    // ---- epilogue A: stage 18x128 offsets in smem ----
    __syncthreads();
    float* s_off = (float*)smem_u;   // [18][128]
    const int p0 = px0 + g, p1 = p0 + 8;
#pragma unroll
    for (int nt = 0; nt < 4; nt++) {
        int oc0 = nt*8 + 2*t4;
        int oc1 = oc0 + 1;
        if (oc0 < COFF) {
            float bv = bias[oc0];
            s_off[oc0*128 + p0] = acc[nt][0] + bv;
            s_off[oc0*128 + p1] = acc[nt][2] + bv;
        }
        if (oc1 < COFF) {
            float bv = bias[oc1];
            s_off[oc1*128 + p0] = acc[nt][1] + bv;
            s_off[oc1*128 + p1] = acc[nt][3] + bv;
        }
    }
    __syncthreads();

    // ---- epilogue B: per (tap,px) bilinear params in regs + 128-channel gather ----
    const float* base = g_h2pad + (size_t)b*C2*HWP;
    for (int e = tid; e < 1152; e += 256) {
        int n  = e >> 7, px = e & 127;
        int hw = hw0 + px;
        int h = hw / W2, w = hw - h*W2;
        float ox = s_off[n*128 + px];
        float oy = s_off[(9+n)*128 + px];
        float pX = (float)(h + 1) + (float)(n/3 - 1) + ox;
        float pY = (float)(w + 1) + (float)(n%3 - 1) + oy;
        float fx = floorf(pX), fy = floorf(pY);
        float qltx = fminf(fmaxf(fx,     0.f), (float)(HP-1));
        float qlty = fminf(fmaxf(fy,     0.f), (float)(WP-1));
        float qrbx = fminf(fmaxf(fx+1.f, 0.f), (float)(HP-1));
        float qrby = fminf(fmaxf(fy+1.f, 0.f), (float)(WP-1));
        bool mx = (pX < 1.f) || (pX > (float)(HP-2));
        bool my = (pY < 1.f) || (pY > (float)(WP-2));
        float pxc = fminf(fmaxf(mx ? fx : pX, 0.f), (float)(HP-1));
        float pyc = fminf(fmaxf(my ? fy : pY, 0.f), (float)(WP-1));
        float glt = (1.f + (qltx - pxc)) * (1.f + (qlty - pyc));
        float grb = (1.f - (qrbx - pxc)) * (1.f - (qrby - pyc));
        float glb = (1.f + (qltx - pxc)) * (1.f - (qrby - pyc));
        float grt = (1.f - (qrbx - pxc)) * (1.f + (qlty - pyc));
        int ix0 = (int)qltx, iy0 = (int)qlty;
        int ix1 = (int)qrbx, iy1 = (int)qrby;
        float m0 = ((unsigned)(ix0-1) < 112u && (unsigned)(iy0-1) < 112u) ? 1.f : 0.f;
        float m1 = ((unsigned)(ix1-1) < 112u && (unsigned)(iy1-1) < 112u) ? 1.f : 0.f;
        float m2 = ((unsigned)(ix0-1) < 112u && (unsigned)(iy1-1) < 112u) ? 1.f : 0.f;
        float m3 = ((unsigned)(ix1-1) < 112u && (unsigned)(iy0-1) < 112u) ? 1.f : 0.f;
        float ts = glt*m0 + grb*m1 + glb*m2 + grt*m3;
        int i00 = ix0*WP + iy0;
        int i11 = ix1*WP + iy1;
        int i01 = ix0*WP + iy1;
        int i10 = ix1*WP + iy0;

        const float* plane = base;
        float* outp = g_xoff + ((size_t)b*K4 + n)*HW2 + hw;
#pragma unroll 4
        for (int ic = 0; ic < C2; ic++) {
            float raw = glt * __ldg(plane + i00)
                      + grb * __ldg(plane + i11)
                      + glb * __ldg(plane + i01)
                      + grt * __ldg(plane + i10);
            float v = raw * s_s[ic] + ts * s_t[ic];
            *outp = __uint_as_float(f2tf32(v));
            plane += HWP;
            outp  += (size_t)9*HW2;
        }
    }
}

// ---------------- deform GEMM: double-buffered 1x-tf32 MMA, 128px x 128oc, kchunk=32 ----------------
__global__ void __launch_bounds__(256, 2)
gemm1x_kernel(const float* __restrict__ X, const unsigned* __restrict__ Wh,
              float* __restrict__ out)
{
    extern __shared__ unsigned smem_u[];
    const int XB = 32*XST;
    const int WB = 32*WST;
    unsigned* sx_base = smem_u;
    unsigned* sw_base = smem_u + 2*XB;

    const int tid = threadIdx.x;
    const int blk = blockIdx.x;
    const int b   = blk / NT128;
    const int hw0 = (blk % NT128) * 128;
    const int lane = tid & 31, wid = tid >> 5;
    const int g = lane >> 2, t4 = lane & 3;

    const int NCHUNK = 36;
    const float* Xb = X + (size_t)b*K4*HW2 + hw0;

    auto load_chunk = [&](int c, int buf) {
        const int k0 = c * 32;
        unsigned* sx = sx_base + buf*XB;
        unsigned* sw = sw_base + buf*WB;
        const uint4* h4 = (const uint4*)(Wh + (size_t)k0*C2);
        for (int e = tid; e < 1024; e += 256) {
            int row = e >> 5, cc = e & 31;
            cp16(sx + row*XST + cc*4, Xb + (size_t)(k0+row)*HW2 + cc*4);
            cp16(sw + row*WST + cc*4, h4 + e);
        }
        cp_commit();
    };

    load_chunk(0, 0);
    float acc[16][4] = {};

    for (int c = 0; c < NCHUNK; c++) {
        const int buf = c & 1;
        cp_wait0();
        __syncthreads();
        if (c + 1 < NCHUNK) load_chunk(c + 1, buf ^ 1);

        const unsigned* sx = sx_base + buf*XB;
        const unsigned* sw = sw_base + buf*WB;
#pragma unroll
        for (int ks = 0; ks < 4; ks++) {
            const unsigned* xp = sx + (ks*8 + t4)*XST + wid*16 + g;
            unsigned a0 = xp[0], a1 = xp[8], a2 = xp[4*XST], a3 = xp[4*XST+8];
            const unsigned* wp = sw + (ks*8 + t4)*WST + g*16;
#pragma unroll
            for (int j = 0; j < 4; j++) {
                uint4 br0 = *(const uint4*)(wp + j*4);
                uint4 br1 = *(const uint4*)(wp + 4*WST + j*4);
                mma_tf32(acc[4*j+0][0],acc[4*j+0][1],acc[4*j+0][2],acc[4*j+0][3],
                         a0,a1,a2,a3, br0.x, br1.x);
                mma_tf32(acc[4*j+1][0],acc[4*j+1][1],acc[4*j+1][2],acc[4*j+1][3],
                         a0,a1,a2,a3, br0.y, br1.y);
                mma_tf32(acc[4*j+2][0],acc[4*j+2][1],acc[4*j+2][2],acc[4*j+2][3],
                         a0,a1,a2,a3, br0.z, br1.z);
                mma_tf32(acc[4*j+3][0],acc[4*j+3][1],acc[4*j+3][2],acc[4*j+3][3],
                         a0,a1,a2,a3, br0.w, br1.w);
            }
        }
        __syncthreads();
    }

    const int p0 = hw0 + wid*16 + g;
    const int p1 = p0 + 8;
#pragma unroll
    for (int nt = 0; nt < 16; nt++) {
        int oc0 = nt*8 + 2*t4;
        int oc1 = oc0 + 1;
        out[((size_t)b*C2 + oc0)*HW2 + p0] = acc[nt][0];
        out[((size_t)b*C2 + oc1)*HW2 + p0] = acc[nt][1];
        out[((size_t)b*C2 + oc0)*HW2 + p1] = acc[nt][2];
        out[((size_t)b*C2 + oc1)*HW2 + p1] = acc[nt][3];
    }
}

// ---------------- launch ----------------
extern "C" void kernel_launch(void* const* d_in, const int* in_sizes, int n_in,
                              void* d_out, int out_size)
{
    const float* x       = (const float*)d_in[0];
    const float* conv1_w = (const float*)d_in[1];
    const float* conv1_b = (const float*)d_in[2];
    const float* bn1_g   = (const float*)d_in[3];
    const float* bn1_b   = (const float*)d_in[4];
    const float* conv2_w = (const float*)d_in[5];
    const float* conv2_b = (const float*)d_in[6];
    const float* bn2_g   = (const float*)d_in[7];
    const float* bn2_b   = (const float*)d_in[8];
    const float* off_w   = (const float*)d_in[9];
    const float* off_b   = (const float*)d_in[10];
    const float* conv4_w = (const float*)d_in[11];
    float* out = (float*)d_out;

    float *p_s1, *p_t1, *p_s2, *p_t2, *p_h2pad, *p_xoff;
    float *p_p1s, *p_p1q, *p_p2s, *p_p2q;
    unsigned *p_w2h, *p_w4h, *p_wOh;
    cudaGetSymbolAddress((void**)&p_s1,    g_scale1);
    cudaGetSymbolAddress((void**)&p_t1,    g_shift1);
    cudaGetSymbolAddress((void**)&p_s2,    g_scale2);
    cudaGetSymbolAddress((void**)&p_t2,    g_shift2);
    cudaGetSymbolAddress((void**)&p_h2pad, g_h2pad);
    cudaGetSymbolAddress((void**)&p_xoff,  g_xoff);
    cudaGetSymbolAddress((void**)&p_p1s,   g_p1s);
    cudaGetSymbolAddress((void**)&p_p1q,   g_p1q);
    cudaGetSymbolAddress((void**)&p_p2s,   g_p2s);
    cudaGetSymbolAddress((void**)&p_p2q,   g_p2q);
    cudaGetSymbolAddress((void**)&p_w2h,   g_w2h);
    cudaGetSymbolAddress((void**)&p_w4h,   g_w4h);
    cudaGetSymbolAddress((void**)&p_wOh,   g_wOh);

    const int SMEM_GEMM = (2*32*XST + 2*32*WST) * 4;           // 68608 B
    const int SMEM_C2F  = SMEM_GEMM + 2*C1*4;                  // 69120 B
    const int SMEM_OFFS = (72*XSO + 72*WSO) * 4 + 2*C2*4;      // 51712 B
    cudaFuncSetAttribute(conv2_fused_kernel,
                         cudaFuncAttributeMaxDynamicSharedMemorySize, SMEM_C2F);
    cudaFuncSetAttribute(gemm1x_kernel,
                         cudaFuncAttributeMaxDynamicSharedMemorySize, SMEM_GEMM);
    cudaFuncSetAttribute(offs_mma_kernel,
                         cudaFuncAttributeMaxDynamicSharedMemorySize, SMEM_OFFS);

    // 0) weight preprocessing (tf32 round + fragment-permuted transpose)
    split_w_kernel<<<(K2*C2 + 255)/256, 256>>>(conv2_w, p_w2h, C1);
    split_w_kernel<<<(K4*C2 + 255)/256, 256>>>(conv4_w, p_w4h, C2);
    split_w_pad_kernel<<<(K4*32 + 255)/256, 256>>>(off_w, p_wOh);

    // 1) conv1 + bias + relu + BN1 partials + 2x2 pool (16x32 tiles)
    {
        dim3 grid(98, 8, BATCH);
        conv1_fused_kernel<<<grid, 128>>>(x, conv1_w, conv1_b);
    }
    // 2) BN1 finalize
    bn_finalize_kernel<<<C1, 256>>>(p_p1s, p_p1q, bn1_g, bn1_b, p_s1, p_t1,
                                    NB1, 1.0f/(float)(BATCH*H1*W1));
    // 3) conv2 fused implicit GEMM (BN1 folded) -> raw padded h2 + BN2 partials
    conv2_fused_kernel<<<GB2, 256, SMEM_C2F>>>(conv2_b, p_h2pad);
    // 4) BN2 finalize
    bn_finalize_kernel<<<C2, 256>>>(p_p2s, p_p2q, bn2_g, bn2_b, p_s2, p_t2,
                                    GB2, 1.0f/(float)(BATCH*HW2));
    // 5) offsets conv (BN2 folded) + fused bilinear params + fused deform gather
    offs_mma_kernel<<<BATCH*NOFF, 256, SMEM_OFFS>>>(off_b);
    // 6) deform GEMM -> d_out
    gemm1x_kernel<<<GB2, 256, SMEM_GEMM>>>(p_xoff, p_w4h, out);
}

// round 17
// speedup vs baseline: 1.0895x; 1.0300x over previous
#include <cuda_runtime.h>
#include <cuda_fp16.h>
#include <math.h>

// ---------------- problem constants ----------------
#define BATCH 4
#define C1    64
#define H1    224
#define W1    224
#define C2    128
#define H2    112
#define W2    112
#define HP    114
#define WP    114
#define HW2   (H2*W2)      // 12544
#define HWP   (HP*WP)      // 12996
#define COFF  18
#define K2    (C1*9)       // 576
#define K4    (C2*9)       // 1152
#define NT128 98           // 128-px tiles per image
#define GB2   (BATCH*NT128) // 392 GEMM blocks
#define NOFF  98

// GEMM smem strides
#define XST 136   // X rows (halves for deform GEMM, words for conv2)
#define WST 132   // W rows (words)

// offsets-kernel smem strides
#define XSO 136
#define WSO 40

// ---------------- scratch (__device__ globals; zero-init, no allocation) ----------------
__device__ float    g_poolpad[BATCH*C1*HWP];        // raw pooled conv1+relu, zero border
__device__ float    g_h2pad[BATCH*C2*HWP];          // raw relu(conv2+bias), zero border
__device__ __align__(16) unsigned g_xoffu[(size_t)BATCH*K4*HW2/2]; // deform X (fp16, BN2 folded)
__device__ unsigned g_w2h[K2*C2];                   // conv2 W^T tf32, frag-permuted [k][g*16+nt]
__device__ unsigned g_w4h[K4*C2];                   // conv4 W^T tf32, frag-permuted
__device__ unsigned g_wOh[K4*32];                   // offsets W^T padded to 32 oc
__device__ float    g_p1s[C1*784], g_p1q[C1*784];   // BN1 per-block partials
__device__ float    g_p2s[C2*GB2], g_p2q[C2*GB2];   // BN2 per-block partials
__device__ float    g_scale1[C1], g_shift1[C1];
__device__ float    g_scale2[C2], g_shift2[C2];

// ---------------- helpers ----------------
__device__ __forceinline__ unsigned f2tf32(float f) {
    unsigned r; asm("cvt.rna.tf32.f32 %0, %1;" : "=r"(r) : "f"(f)); return r;
}
__device__ __forceinline__ void mma_tf32(float& d0, float& d1, float& d2, float& d3,
                                         unsigned a0, unsigned a1, unsigned a2, unsigned a3,
                                         unsigned b0, unsigned b1) {
    asm volatile("mma.sync.aligned.m16n8k8.row.col.f32.tf32.tf32.f32 "
                 "{%0,%1,%2,%3},{%4,%5,%6,%7},{%8,%9},{%0,%1,%2,%3};"
                 : "+f"(d0), "+f"(d1), "+f"(d2), "+f"(d3)
                 : "r"(a0), "r"(a1), "r"(a2), "r"(a3), "r"(b0), "r"(b1));
}
__device__ __forceinline__ void cp16(void* dst, const void* src) {
    unsigned d = (unsigned)__cvta_generic_to_shared(dst);
    asm volatile("cp.async.cg.shared.global [%0], [%1], 16;" :: "r"(d), "l"(src));
}
__device__ __forceinline__ void cp_commit() { asm volatile("cp.async.commit_group;"); }
__device__ __forceinline__ void cp_wait1()  { asm volatile("cp.async.wait_group 1;" ::: "memory"); }
__device__ __forceinline__ void cp_wait0()  { asm volatile("cp.async.wait_group 0;" ::: "memory"); }

// ---------------- weight prep: tf32 round + permute (ic-major K: k = ic*9+n) ----------------
__global__ void __launch_bounds__(256)
split_w_kernel(const float* __restrict__ w, unsigned* __restrict__ wh,
               int C_in)
{
    int idx = blockIdx.x * 256 + threadIdx.x;
    int total = C_in * 9 * 128;
    if (idx >= total) return;
    int rem = idx & 127;
    int k   = idx >> 7;
    int g   = rem >> 4, nt = rem & 15;
    int oc  = nt*8 + g;
    int ic = k / 9, n = k % 9;
    wh[idx] = f2tf32(w[((size_t)oc*C_in + ic)*9 + n]);
}

__global__ void __launch_bounds__(256)
split_w_pad_kernel(const float* __restrict__ w, unsigned* __restrict__ wh)
{
    int idx = blockIdx.x * 256 + threadIdx.x;
    int total = K4 * 32;
    if (idx >= total) return;
    int oc = idx % 32;
    int r  = idx / 32;
    int ic = r / 9, n = r % 9;
    float v = (oc < COFF) ? w[((size_t)oc*C2 + ic)*9 + n] : 0.f;
    wh[idx] = f2tf32(v);
}

// ---------------- conv1 fused: conv + bias + relu + BN1 partials + 2x2 pool ----------------
__global__ void __launch_bounds__(128)
conv1_fused_kernel(const float* __restrict__ x, const float* __restrict__ wgt,
                   const float* __restrict__ bias)
{
    __shared__ float s_in[3][18][18];
    __shared__ float s_w[8][3][9];
    __shared__ float s_red[2][8][4];

    const int tileX  = (blockIdx.x % 14) * 16;
    const int tileY  = (blockIdx.x / 14) * 16;
    const int ocBase = blockIdx.y * 8;
    const int b      = blockIdx.z;
    const int tid    = threadIdx.x;
    const int tx     = tid & 15;
    const int ty     = tid >> 4;

    for (int e = tid; e < 3*18*18; e += 128) {
        int ic = e / 324;
        int r  = (e / 18) % 18;
        int c  = e % 18;
        int gy = tileY + r - 1, gx = tileX + c - 1;
        float v = 0.f;
        if (gy >= 0 && gy < H1 && gx >= 0 && gx < W1)
            v = x[(((size_t)b*3 + ic)*H1 + gy)*W1 + gx];
        s_in[ic][r][c] = v;
    }
    for (int e = tid; e < 8*27; e += 128) {
        int oc = e / 27, r = e % 27;
        int ic = r / 9, k = r % 9;
        s_w[oc][ic][k] = wgt[((size_t)(ocBase+oc)*3 + ic)*9 + k];
    }
    __syncthreads();

    float acc0[8], acc1[8];
#pragma unroll
    for (int i = 0; i < 8; i++) { acc0[i] = 0.f; acc1[i] = 0.f; }
    const int y0 = ty * 2;
#pragma unroll
    for (int ic = 0; ic < 3; ic++) {
        float r[4][3];
#pragma unroll
        for (int rr = 0; rr < 4; rr++)
#pragma unroll
            for (int cc = 0; cc < 3; cc++)
                r[rr][cc] = s_in[ic][y0+rr][tx+cc];
#pragma unroll
        for (int oc = 0; oc < 8; oc++) {
            float a0 = acc0[oc], a1 = acc1[oc];
#pragma unroll
            for (int k = 0; k < 9; k++) {
                float wv = s_w[oc][ic][k];
                a0 = fmaf(r[k/3  ][k%3], wv, a0);
                a1 = fmaf(r[k/3+1][k%3], wv, a1);
            }
            acc0[oc] = a0; acc1[oc] = a1;
        }
    }

    const int warp = tid >> 5, lane = tid & 31;
    const int prow = (tileY >> 1) + ty + 1;
    const int pcol = (tileX >> 1) + (tx >> 1) + 1;
    const int blkId = blockIdx.x + 196 * blockIdx.z;

#pragma unroll
    for (int oc = 0; oc < 8; oc++) {
        float bv = bias[ocBase + oc];
        float v0 = fmaxf(acc0[oc] + bv, 0.f);
        float v1 = fmaxf(acc1[oc] + bv, 0.f);
        float pv = v0 + v1;
        float po = pv + __shfl_xor_sync(0xffffffffu, pv, 1);
        if ((tx & 1) == 0)
            g_poolpad[(((size_t)b*C1 + ocBase + oc)*HP + prow)*WP + pcol] = 0.25f * po;
        float s = pv, q = v0*v0 + v1*v1;
#pragma unroll
        for (int o = 16; o; o >>= 1) {
            s += __shfl_down_sync(0xffffffffu, s, o);
            q += __shfl_down_sync(0xffffffffu, q, o);
        }
        if (lane == 0) { s_red[0][oc][warp] = s; s_red[1][oc][warp] = q; }
    }
    __syncthreads();
    if (tid < 8) {
        float S = s_red[0][tid][0] + s_red[0][tid][1] + s_red[0][tid][2] + s_red[0][tid][3];
        float Q = s_red[1][tid][0] + s_red[1][tid][1] + s_red[1][tid][2] + s_red[1][tid][3];
        g_p1s[(size_t)(ocBase + tid)*784 + blkId] = S;
        g_p1q[(size_t)(ocBase + tid)*784 + blkId] = Q;
    }
}

// ---------------- BN finalize ----------------
__global__ void __launch_bounds__(256)
bn_finalize_kernel(const float* __restrict__ ps, const float* __restrict__ pq,
                   const float* __restrict__ gamma, const float* __restrict__ beta,
                   float* __restrict__ scale, float* __restrict__ shift,
                   int nblk, float inv_count)
{
    const int c = blockIdx.x;
    const int tid = threadIdx.x;
    float s = 0.f, q = 0.f;
    for (int i = tid; i < nblk; i += 256) {
        s += ps[(size_t)c*nblk + i];
        q += pq[(size_t)c*nblk + i];
    }
    __shared__ float sh[64];
#pragma unroll
    for (int o = 16; o; o >>= 1) {
        s += __shfl_down_sync(0xffffffffu, s, o);
        q += __shfl_down_sync(0xffffffffu, q, o);
    }
    int warp = tid >> 5, lane = tid & 31;
    if (lane == 0) { sh[warp] = s; sh[32+warp] = q; }
    __syncthreads();
    if (warp == 0) {
        s = (lane < 8) ? sh[lane]    : 0.f;
        q = (lane < 8) ? sh[32+lane] : 0.f;
#pragma unroll
        for (int o = 4; o; o >>= 1) {
            s += __shfl_down_sync(0xffffffffu, s, o);
            q += __shfl_down_sync(0xffffffffu, q, o);
        }
        if (lane == 0) {
            float mean = s * inv_count;
            float var  = q * inv_count - mean*mean;
            float inv  = rsqrtf(var + 1e-5f);
            float sc   = gamma[c] * inv;
            scale[c] = sc;
            shift[c] = beta[c] - mean * sc;
        }
    }
}

// ---------------- conv2 fused implicit GEMM: in-kernel im2col (BN1 fold) + 1x-tf32 MMA ----------------
__global__ void __launch_bounds__(256, 2)
conv2_fused_kernel(const float* __restrict__ bias, float* __restrict__ outpad)
{
    extern __shared__ unsigned smem_u[];
    const int XB = 32*XST;
    const int WB = 32*WST;
    unsigned* sx_base = smem_u;
    unsigned* sw_base = smem_u + 2*XB;
    float* s_s = (float*)(sw_base + 2*WB);        // 64
    float* s_t = s_s + C1;                        // 64

    const int tid = threadIdx.x;
    const int blk = blockIdx.x;
    const int b   = blk / NT128;
    const int hw0 = (blk % NT128) * 128;
    const int lane = tid & 31, wid = tid >> 5;
    const int g = lane >> 2, t4 = lane & 3;

    if (tid < C1)        s_s[tid] = g_scale1[tid];
    else if (tid < 2*C1) s_t[tid - C1] = g_shift1[tid - C1];

    const float* inb = g_poolpad + (size_t)b*C1*HWP;

    auto loadW = [&](int c, int buf) {
        unsigned* sw = sw_base + buf*WB;
        const uint4* h4 = (const uint4*)(g_w2h + (size_t)(c*32)*C2);
        for (int e = tid; e < 1024; e += 256) {
            int row = e >> 5, cc = e & 31;
            cp16(sw + row*WST + cc*4, h4 + e);
        }
        cp_commit();
    };
    auto gatherX = [&](int c, int buf) {
        unsigned* sx = sx_base + buf*XB;
        const int k0 = c * 32;
#pragma unroll 4
        for (int e = tid; e < 4096; e += 256) {
            int row = e >> 7, px = e & 127;
            int kr = k0 + row;
            int ic = kr / 9, n = kr - ic*9;
            int hw = hw0 + px;
            int h  = hw / W2, w = hw - h*W2;
            int hh = h + n/3, ww = w + n - (n/3)*3;
            float raw = inb[(size_t)ic*HWP + hh*WP + ww];
            float m = ((unsigned)(hh-1) < 112u && (unsigned)(ww-1) < 112u) ? 1.f : 0.f;
            float v = raw * s_s[ic] + m * s_t[ic];
            sx[row*XST + px] = f2tf32(v);
        }
    };

    loadW(0, 0);
    __syncthreads();   // s_s/s_t visible
    float acc[16][4] = {};

    const int NCHUNK = 18;
    for (int c = 0; c < NCHUNK; c++) {
        const int buf = c & 1;
        if (c + 1 < NCHUNK) loadW(c + 1, buf ^ 1);
        gatherX(c, buf);
        if (c + 1 < NCHUNK) cp_wait1(); else cp_wait0();
        __syncthreads();

        const unsigned* sx = sx_base + buf*XB;
        const unsigned* sw = sw_base + buf*WB;
#pragma unroll
        for (int ks = 0; ks < 4; ks++) {
            const unsigned* xp = sx + (ks*8 + t4)*XST + wid*16 + g;
            unsigned a0 = xp[0], a1 = xp[8], a2 = xp[4*XST], a3 = xp[4*XST+8];
            const unsigned* wp = sw + (ks*8 + t4)*WST + g*16;
#pragma unroll
            for (int j = 0; j < 4; j++) {
                uint4 br0 = *(const uint4*)(wp + j*4);
                uint4 br1 = *(const uint4*)(wp + 4*WST + j*4);
                mma_tf32(acc[4*j+0][0],acc[4*j+0][1],acc[4*j+0][2],acc[4*j+0][3],
                         a0,a1,a2,a3, br0.x, br1.x);
                mma_tf32(acc[4*j+1][0],acc[4*j+1][1],acc[4*j+1][2],acc[4*j+1][3],
                         a0,a1,a2,a3, br0.y, br1.y);
                mma_tf32(acc[4*j+2][0],acc[4*j+2][1],acc[4*j+2][2],acc[4*j+2][3],
                         a0,a1,a2,a3, br0.z, br1.z);
                mma_tf32(acc[4*j+3][0],acc[4*j+3][1],acc[4*j+3][2],acc[4*j+3][3],
                         a0,a1,a2,a3, br0.w, br1.w);
            }
        }
        __syncthreads();
    }

    const int p0 = hw0 + wid*16 + g;
    const int p1 = p0 + 8;
    float* s_red = (float*)smem_u;    // [8][128][2] floats
    const int h0 = p0 / W2, w0 = p0 - h0*W2;
    const int h1 = p1 / W2, w1 = p1 - h1*W2;
#pragma unroll
    for (int nt = 0; nt < 16; nt++) {
        int oc0 = nt*8 + 2*t4;
        int oc1 = oc0 + 1;
        float b0v = bias[oc0], b1v = bias[oc1];
        float v00 = fmaxf(acc[nt][0] + b0v, 0.f);
        float v01 = fmaxf(acc[nt][1] + b1v, 0.f);
        float v10 = fmaxf(acc[nt][2] + b0v, 0.f);
        float v11 = fmaxf(acc[nt][3] + b1v, 0.f);
        outpad[(((size_t)b*C2 + oc0)*HP + h0+1)*WP + w0+1] = v00;
        outpad[(((size_t)b*C2 + oc1)*HP + h0+1)*WP + w0+1] = v01;
        outpad[(((size_t)b*C2 + oc0)*HP + h1+1)*WP + w1+1] = v10;
        outpad[(((size_t)b*C2 + oc1)*HP + h1+1)*WP + w1+1] = v11;
        float s0 = v00 + v10, q0 = v00*v00 + v10*v10;
        float s1 = v01 + v11, q1 = v01*v01 + v11*v11;
#pragma unroll
        for (int o = 4; o <= 16; o <<= 1) {
            s0 += __shfl_xor_sync(0xffffffffu, s0, o);
            q0 += __shfl_xor_sync(0xffffffffu, q0, o);
            s1 += __shfl_xor_sync(0xffffffffu, s1, o);
            q1 += __shfl_xor_sync(0xffffffffu, q1, o);
        }
        if (g == 0) {
            s_red[(wid*128 + oc0)*2 + 0] = s0;
            s_red[(wid*128 + oc0)*2 + 1] = q0;
            s_red[(wid*128 + oc1)*2 + 0] = s1;
            s_red[(wid*128 + oc1)*2 + 1] = q1;
        }
    }
    __syncthreads();
    if (tid < 128) {
        float S = 0.f, Q = 0.f;
#pragma unroll
        for (int w = 0; w < 8; w++) {
            S += s_red[(w*128 + tid)*2 + 0];
            Q += s_red[(w*128 + tid)*2 + 1];
        }
        g_p2s[(size_t)tid*GB2 + blk] = S;
        g_p2q[(size_t)tid*GB2 + blk] = Q;
    }
}

// ---------------- offsets conv + fused bilinear params + fused deform gather (fp16 out) ----------------
__global__ void __launch_bounds__(256)
offs_mma_kernel(const float* __restrict__ bias)
{
    extern __shared__ unsigned smem_u[];
    unsigned* s_x  = smem_u;
    unsigned* s_w  = s_x + 72*XSO;
    float*    s_s  = (float*)(s_w + 72*WSO);
    float*    s_t  = s_s + C2;

    const int tid  = threadIdx.x;
    const int blk  = blockIdx.x;
    const int b    = blk / NOFF;
    const int hw0  = (blk % NOFF) * 128;
    const int lane = tid & 31, wid = tid >> 5;
    const int g    = lane >> 2, t4 = lane & 3;
    const int px0  = wid * 16;

    if (tid < C2) { s_s[tid] = g_scale2[tid]; s_t[tid] = g_shift2[tid]; }

    const float* inb = g_h2pad + (size_t)b*C2*HWP;
    float acc[4][4] = {};

    for (int ic0 = 0; ic0 < C2; ic0 += 8) {
        __syncthreads();
        {
            const uint4* sh4 = (const uint4*)(g_wOh + (size_t)ic0*9*32);
            for (int e = tid; e < 576; e += 256) {
                int kr = e >> 3, c4 = e & 7;
                cp16(s_w + kr*WSO + c4*4, sh4 + e);
            }
        }
        for (int e = tid; e < 9216; e += 256) {
            int r  = e >> 7, px = e & 127;
            int icr = r / 9, n = r - icr*9;
            int hw = hw0 + px;
            int h  = hw / W2, w = hw - h*W2;
            int hh = h + n/3, ww = w + n%3;
            float raw = inb[(size_t)(ic0+icr)*HWP + hh*WP + ww];
            float m = ((unsigned)(hh-1) < 112u && (unsigned)(ww-1) < 112u) ? 1.f : 0.f;
            float v = raw * s_s[ic0+icr] + m * s_t[ic0+icr];
            s_x[r*XSO + px] = f2tf32(v);
        }
        cp_commit(); cp_wait0();
        __syncthreads();

#pragma unroll
        for (int ks = 0; ks < 9; ks++) {
            const unsigned* xp = s_x + (ks*8 + t4)*XSO + px0 + g;
            unsigned a0 = xp[0], a1 = xp[8], a2 = xp[4*XSO], a3 = xp[4*XSO+8];
            const unsigned* wp = s_w + (ks*8 + t4)*WSO + g;
#pragma unroll
            for (int nt = 0; nt < 4; nt++) {
                unsigned b0 = wp[nt*8], b1 = wp[4*WSO + nt*8];
                mma_tf32(acc[nt][0],acc[nt][1],acc[nt][2],acc[nt][3], a0,a1,a2,a3, b0,b1);
            }
        }
    }

    // ---- epilogue A: stage 18x128 offsets in smem ----
    __syncthreads();
    float* s_off = (float*)smem_u;   // [18][128]
    const int p0 = px0 + g, p1 = p0 + 8;
#pragma unroll
    for (int nt = 0; nt < 4; nt++) {
        int oc0 = nt*8 + 2*t4;
        int oc1 = oc0 + 1;
        if (oc0 < COFF) {
            float bv = bias[oc0];
            s_off[oc0*128 + p0] = acc[nt][0] + bv;
            s_off[oc0*128 + p1] = acc[nt][2] + bv;
        }
        if (oc1 < COFF) {
            float bv = bias[oc1];
            s_off[oc1*128 + p0] = acc[nt][1] + bv;
            s_off[oc1*128 + p1] = acc[nt][3] + bv;
        }
    }
    __syncthreads();

    // ---- epilogue B: per (tap,px) bilinear params in regs + 128-channel gather (fp16) ----
    __half* xoff = (__half*)g_xoffu;
    const float* base = g_h2pad + (size_t)b*C2*HWP;
    for (int e = tid; e < 1152; e += 256) {
        int n  = e >> 7, px = e & 127;
        int hw = hw0 + px;
        int h = hw / W2, w = hw - h*W2;
        float ox = s_off[n*128 + px];
        float oy = s_off[(9+n)*128 + px];
        float pX = (float)(h + 1) + (float)(n/3 - 1) + ox;
        float pY = (float)(w + 1) + (float)(n%3 - 1) + oy;
        float fx = floorf(pX), fy = floorf(pY);
        float qltx = fminf(fmaxf(fx,     0.f), (float)(HP-1));
        float qlty = fminf(fmaxf(fy,     0.f), (float)(WP-1));
        float qrbx = fminf(fmaxf(fx+1.f, 0.f), (float)(HP-1));
        float qrby = fminf(fmaxf(fy+1.f, 0.f), (float)(WP-1));
        bool mx = (pX < 1.f) || (pX > (float)(HP-2));
        bool my = (pY < 1.f) || (pY > (float)(WP-2));
        float pxc = fminf(fmaxf(mx ? fx : pX, 0.f), (float)(HP-1));
        float pyc = fminf(fmaxf(my ? fy : pY, 0.f), (float)(WP-1));
        float glt = (1.f + (qltx - pxc)) * (1.f + (qlty - pyc));
        float grb = (1.f - (qrbx - pxc)) * (1.f - (qrby - pyc));
        float glb = (1.f + (qltx - pxc)) * (1.f - (qrby - pyc));
        float grt = (1.f - (qrbx - pxc)) * (1.f + (qlty - pyc));
        int ix0 = (int)qltx, iy0 = (int)qlty;
        int ix1 = (int)qrbx, iy1 = (int)qrby;
        float m0 = ((unsigned)(ix0-1) < 112u && (unsigned)(iy0-1) < 112u) ? 1.f : 0.f;
        float m1 = ((unsigned)(ix1-1) < 112u && (unsigned)(iy1-1) < 112u) ? 1.f : 0.f;
        float m2 = ((unsigned)(ix0-1) < 112u && (unsigned)(iy1-1) < 112u) ? 1.f : 0.f;
        float m3 = ((unsigned)(ix1-1) < 112u && (unsigned)(iy0-1) < 112u) ? 1.f : 0.f;
        float ts = glt*m0 + grb*m1 + glb*m2 + grt*m3;
        int i00 = ix0*WP + iy0;
        int i11 = ix1*WP + iy1;
        int i01 = ix0*WP + iy1;
        int i10 = ix1*WP + iy0;

        const float* plane = base;
        __half* outp = xoff + ((size_t)b*K4 + n)*HW2 + hw;
#pragma unroll 4
        for (int ic = 0; ic < C2; ic++) {
            float raw = glt * __ldg(plane + i00)
                      + grb * __ldg(plane + i11)
                      + glb * __ldg(plane + i01)
                      + grt * __ldg(plane + i10);
            float v = raw * s_s[ic] + ts * s_t[ic];
            *outp = __float2half_rn(v);
            plane += HWP;
            outp  += (size_t)9*HW2;
        }
    }
}

// ---------------- deform GEMM: double-buffered 1x-tf32 MMA, fp16 X, 128px x 128oc ----------------
__global__ void __launch_bounds__(256, 2)
gemm1x_kernel(const unsigned* __restrict__ Xu, const unsigned* __restrict__ Wh,
              float* __restrict__ out)
{
    extern __shared__ unsigned smem_u[];
    const int XBH = 32*XST;                // halves per X stage
    const int WB  = 32*WST;                // words per W stage
    __half*   sxh     = (__half*)smem_u;               // 2 X stages (halves)
    unsigned* sw_base = smem_u + (2*XBH)/2;            // 2 W stages (words)

    const int tid = threadIdx.x;
    const int blk = blockIdx.x;
    const int b   = blk / NT128;
    const int hw0 = (blk % NT128) * 128;
    const int lane = tid & 31, wid = tid >> 5;
    const int g = lane >> 2, t4 = lane & 3;

    const int NCHUNK = 36;
    const __half* Xb = (const __half*)Xu + (size_t)b*K4*HW2 + hw0;

    auto load_chunk = [&](int c, int buf) {
        const int k0 = c * 32;
        __half*   sx = sxh + buf*XBH;
        unsigned* sw = sw_base + buf*WB;
        // X: 32 rows x 128 halves = 512 cp16
        for (int e = tid; e < 512; e += 256) {
            int row = e >> 4, cc = e & 15;
            cp16(sx + row*XST + cc*8, Xb + (size_t)(k0+row)*HW2 + cc*8);
        }
        // W: 32 rows x 128 words = 1024 cp16
        const uint4* h4 = (const uint4*)(Wh + (size_t)k0*C2);
        for (int e = tid; e < 1024; e += 256) {
            int row = e >> 5, cc = e & 31;
            cp16(sw + row*WST + cc*4, h4 + e);
        }
        cp_commit();
    };

    load_chunk(0, 0);
    float acc[16][4] = {};

    for (int c = 0; c < NCHUNK; c++) {
        const int buf = c & 1;
        cp_wait0();
        __syncthreads();
        if (c + 1 < NCHUNK) load_chunk(c + 1, buf ^ 1);

        const __half*   sx = sxh + buf*XBH;
        const unsigned* sw = sw_base + buf*WB;
#pragma unroll
        for (int ks = 0; ks < 4; ks++) {
            const __half* xp = sx + (ks*8 + t4)*XST + wid*16 + g;
            unsigned a0 = __float_as_uint(__half2float(xp[0]));
            unsigned a1 = __float_as_uint(__half2float(xp[8]));
            unsigned a2 = __float_as_uint(__half2float(xp[4*XST]));
            unsigned a3 = __float_as_uint(__half2float(xp[4*XST+8]));
            const unsigned* wp = sw + (ks*8 + t4)*WST + g*16;
#pragma unroll
            for (int j = 0; j < 4; j++) {
                uint4 br0 = *(const uint4*)(wp + j*4);
                uint4 br1 = *(const uint4*)(wp + 4*WST + j*4);
                mma_tf32(acc[4*j+0][0],acc[4*j+0][1],acc[4*j+0][2],acc[4*j+0][3],
                         a0,a1,a2,a3, br0.x, br1.x);
                mma_tf32(acc[4*j+1][0],acc[4*j+1][1],acc[4*j+1][2],acc[4*j+1][3],
                         a0,a1,a2,a3, br0.y, br1.y);
                mma_tf32(acc[4*j+2][0],acc[4*j+2][1],acc[4*j+2][2],acc[4*j+2][3],
                         a0,a1,a2,a3, br0.z, br1.z);
                mma_tf32(acc[4*j+3][0],acc[4*j+3][1],acc[4*j+3][2],acc[4*j+3][3],
                         a0,a1,a2,a3, br0.w, br1.w);
            }
        }
        __syncthreads();
    }

    const int p0 = hw0 + wid*16 + g;
    const int p1 = p0 + 8;
#pragma unroll
    for (int nt = 0; nt < 16; nt++) {
        int oc0 = nt*8 + 2*t4;
        int oc1 = oc0 + 1;
        out[((size_t)b*C2 + oc0)*HW2 + p0] = acc[nt][0];
        out[((size_t)b*C2 + oc1)*HW2 + p0] = acc[nt][1];
        out[((size_t)b*C2 + oc0)*HW2 + p1] = acc[nt][2];
        out[((size_t)b*C2 + oc1)*HW2 + p1] = acc[nt][3];
    }
}

// ---------------- launch ----------------
extern "C" void kernel_launch(void* const* d_in, const int* in_sizes, int n_in,
                              void* d_out, int out_size)
{
    const float* x       = (const float*)d_in[0];
    const float* conv1_w = (const float*)d_in[1];
    const float* conv1_b = (const float*)d_in[2];
    const float* bn1_g   = (const float*)d_in[3];
    const float* bn1_b   = (const float*)d_in[4];
    const float* conv2_w = (const float*)d_in[5];
    const float* conv2_b = (const float*)d_in[6];
    const float* bn2_g   = (const float*)d_in[7];
    const float* bn2_b   = (const float*)d_in[8];
    const float* off_w   = (const float*)d_in[9];
    const float* off_b   = (const float*)d_in[10];
    const float* conv4_w = (const float*)d_in[11];
    float* out = (float*)d_out;

    float *p_s1, *p_t1, *p_s2, *p_t2, *p_h2pad;
    float *p_p1s, *p_p1q, *p_p2s, *p_p2q;
    unsigned *p_w2h, *p_w4h, *p_wOh, *p_xoffu;
    cudaGetSymbolAddress((void**)&p_s1,    g_scale1);
    cudaGetSymbolAddress((void**)&p_t1,    g_shift1);
    cudaGetSymbolAddress((void**)&p_s2,    g_scale2);
    cudaGetSymbolAddress((void**)&p_t2,    g_shift2);
    cudaGetSymbolAddress((void**)&p_h2pad, g_h2pad);
    cudaGetSymbolAddress((void**)&p_xoffu, g_xoffu);
    cudaGetSymbolAddress((void**)&p_p1s,   g_p1s);
    cudaGetSymbolAddress((void**)&p_p1q,   g_p1q);
    cudaGetSymbolAddress((void**)&p_p2s,   g_p2s);
    cudaGetSymbolAddress((void**)&p_p2q,   g_p2q);
    cudaGetSymbolAddress((void**)&p_w2h,   g_w2h);
    cudaGetSymbolAddress((void**)&p_w4h,   g_w4h);
    cudaGetSymbolAddress((void**)&p_wOh,   g_wOh);

    const int SMEM_C2F  = (2*32*XST + 2*32*WST) * 4 + 2*C1*4;          // 69120 B
    const int SMEM_GEMM = (2*32*XST) * 2 + (2*32*WST) * 4;             // 51200 B
    const int SMEM_OFFS = (72*XSO + 72*WSO) * 4 + 2*C2*4;              // 51712 B
    cudaFuncSetAttribute(conv2_fused_kernel,
                         cudaFuncAttributeMaxDynamicSharedMemorySize, SMEM_C2F);
    cudaFuncSetAttribute(gemm1x_kernel,
                         cudaFuncAttributeMaxDynamicSharedMemorySize, SMEM_GEMM);
    cudaFuncSetAttribute(offs_mma_kernel,
                         cudaFuncAttributeMaxDynamicSharedMemorySize, SMEM_OFFS);

    // 0) weight preprocessing (tf32 round + fragment-permuted transpose)
    split_w_kernel<<<(K2*C2 + 255)/256, 256>>>(conv2_w, p_w2h, C1);
    split_w_kernel<<<(K4*C2 + 255)/256, 256>>>(conv4_w, p_w4h, C2);
    split_w_pad_kernel<<<(K4*32 + 255)/256, 256>>>(off_w, p_wOh);

    // 1) conv1 + bias + relu + BN1 partials + 2x2 pool
    {
        dim3 grid(196, 8, BATCH);
        conv1_fused_kernel<<<grid, 128>>>(x, conv1_w, conv1_b);
    }
    // 2) BN1 finalize
    bn_finalize_kernel<<<C1, 256>>>(p_p1s, p_p1q, bn1_g, bn1_b, p_s1, p_t1,
                                    784, 1.0f/(float)(BATCH*H1*W1));
    // 3) conv2 fused implicit GEMM (BN1 folded) -> raw padded h2 + BN2 partials
    conv2_fused_kernel<<<GB2, 256, SMEM_C2F>>>(conv2_b, p_h2pad);
    // 4) BN2 finalize
    bn_finalize_kernel<<<C2, 256>>>(p_p2s, p_p2q, bn2_g, bn2_b, p_s2, p_t2,
                                    GB2, 1.0f/(float)(BATCH*HW2));
    // 5) offsets conv (BN2 folded) + fused bilinear params + fused deform gather (fp16)
    offs_mma_kernel<<<BATCH*NOFF, 256, SMEM_OFFS>>>(off_b);
    // 6) deform GEMM (fp16 X) -> d_out
    gemm1x_kernel<<<GB2, 256, SMEM_GEMM>>>(p_xoffu, p_w4h, out);
}